// round 17
// baseline (speedup 1.0000x reference)
#include <cuda_runtime.h>
#include <cuda_bf16.h>
#include <math.h>
#include <cstdint>

// Problem constants
#define BB 4
#define TT 2048
#define CC 1024
#define HH 16
#define HS 64
#define MM (BB*TT)   // 8192

// ---------------------------------------------------------------------------
// Scratch (device globals: no allocations allowed)
// ---------------------------------------------------------------------------
__device__ __nv_bfloat16 g_xhi[(size_t)MM*CC],  g_xlo[(size_t)MM*CC];
__device__ __nv_bfloat16 g_wt_hi[(size_t)3*HH*HS*CC], g_wt_lo[(size_t)3*HH*HS*CC]; // W^T: [which][h*HS+d][c]
__device__ __nv_bfloat16 g_wo_hi[(size_t)CC*CC], g_wo_lo[(size_t)CC*CC];           // [n][k]
__device__ __nv_bfloat16 g_qhi[(size_t)BB*HH*TT*HS], g_qlo[(size_t)BB*HH*TT*HS];   // [B,H,T,HS]
__device__ __nv_bfloat16 g_khi[(size_t)BB*HH*TT*HS], g_klo[(size_t)BB*HH*TT*HS];   // [B,H,T,HS]
__device__ __nv_bfloat16 g_vthi[(size_t)BB*HH*HS*TT], g_vtlo[(size_t)BB*HH*HS*TT]; // [B,H,HS,T] (V^T)
__device__ __nv_bfloat16 g_yhi[(size_t)MM*CC],  g_ylo[(size_t)MM*CC];              // [B,T,C]

// ---------------------------------------------------------------------------
// PTX helpers (compute_103-safe: sm_80+ mma.sync / ldmatrix / cp.async)
// ---------------------------------------------------------------------------
__device__ __forceinline__ uint32_t smem_u32(const void* p) {
    uint32_t a;
    asm("{ .reg .u64 t; cvta.to.shared.u64 t, %1; cvt.u32.u64 %0, t; }"
        : "=r"(a) : "l"(p));
    return a;
}

#define LDSM4(r, addr) \
    asm volatile("ldmatrix.sync.aligned.m8n8.x4.shared.b16 {%0,%1,%2,%3}, [%4];" \
        : "=r"((r)[0]), "=r"((r)[1]), "=r"((r)[2]), "=r"((r)[3]) : "r"(addr))

#define MMA_BF16(c, a, b) \
    asm volatile("mma.sync.aligned.m16n8k16.row.col.f32.bf16.bf16.f32 " \
        "{%0,%1,%2,%3}, {%4,%5,%6,%7}, {%8,%9}, {%0,%1,%2,%3};" \
        : "+f"((c)[0]), "+f"((c)[1]), "+f"((c)[2]), "+f"((c)[3]) \
        : "r"((a)[0]), "r"((a)[1]), "r"((a)[2]), "r"((a)[3]), \
          "r"((b)[0]), "r"((b)[1]))

#define CP_ASYNC16(saddr, gptr) \
    asm volatile("cp.async.cg.shared.global [%0], [%1], 16;" \
        :: "r"(saddr), "l"(gptr) : "memory")
#define CP_COMMIT() asm volatile("cp.async.commit_group;" ::: "memory")
#define CP_WAIT0()  asm volatile("cp.async.wait_group 0;" ::: "memory")

__device__ __forceinline__ void split1(float v, __nv_bfloat16& h, __nv_bfloat16& l) {
    h = __float2bfloat16(v);
    l = __float2bfloat16(v - __bfloat162float(h));
}
__device__ __forceinline__ uint32_t packb(__nv_bfloat16 a, __nv_bfloat16 b) {
    return (uint32_t)__bfloat16_as_ushort(a) | ((uint32_t)__bfloat16_as_ushort(b) << 16);
}
__device__ __forceinline__ void split2(float v0, float v1, uint32_t& hi, uint32_t& lo) {
    __nv_bfloat16 h0, l0, h1, l1;
    split1(v0, h0, l0); split1(v1, h1, l1);
    hi = packb(h0, h1); lo = packb(l0, l1);
}

// ---------------------------------------------------------------------------
// Prep kernels: fp32 -> (hi, lo) bf16
// ---------------------------------------------------------------------------
__global__ __launch_bounds__(256) void cvt_split(const float* __restrict__ s,
                                                 __nv_bfloat16* __restrict__ hi,
                                                 __nv_bfloat16* __restrict__ lo)
{
    size_t i4 = (size_t)blockIdx.x * 256 + threadIdx.x;
    float4 v = reinterpret_cast<const float4*>(s)[i4];
    __nv_bfloat16 h[4], l[4];
    split1(v.x, h[0], l[0]); split1(v.y, h[1], l[1]);
    split1(v.z, h[2], l[2]); split1(v.w, h[3], l[3]);
    reinterpret_cast<uint2*>(hi)[i4] = make_uint2(packb(h[0], h[1]), packb(h[2], h[3]));
    reinterpret_cast<uint2*>(lo)[i4] = make_uint2(packb(l[0], l[1]), packb(l[2], l[3]));
}

__global__ void cvt_w_t(const float* __restrict__ Wq,
                        const float* __restrict__ Wk,
                        const float* __restrict__ Wv)
{
    __shared__ float ts[32][33];
    const int which = blockIdx.z / HH;
    const int h     = blockIdx.z % HH;
    const float* W  = (which == 0) ? Wq : (which == 1) ? Wk : Wv;
    const int c0 = blockIdx.x * 32;
    const int d0 = blockIdx.y * 32;

    for (int i = threadIdx.y; i < 32; i += 8)
        ts[i][threadIdx.x] = W[((size_t)h * CC + c0 + i) * HS + d0 + threadIdx.x];
    __syncthreads();

    __nv_bfloat16* hi = g_wt_hi + (size_t)which * HH * HS * CC;
    __nv_bfloat16* lo = g_wt_lo + (size_t)which * HH * HS * CC;
    for (int i = threadIdx.y; i < 32; i += 8) {
        int d = d0 + i, c = c0 + threadIdx.x;
        float v = ts[threadIdx.x][i];
        __nv_bfloat16 vh, vl;
        split1(v, vh, vl);
        size_t o = (size_t)(h * HS + d) * CC + c;
        hi[o] = vh;
        lo[o] = vl;
    }
}

// ---------------------------------------------------------------------------
// FUSED QKV GEMM: one block computes q, k, AND v for (m-tile, head).
// A-fragments are loaded once per k-step and reused for all 3 B operands:
// per warp per ks: 16 LDSM vs 72 MMA (ratio 4.5, up from 3.0).
// Block tile 128(m) x 64(n=head) x 64(k); warps 4m x 2n (warp tile 32x32).
// Stage (80KB): AHI 0, ALO 16K, then per z: BHI/BLO 8K each at 32K+z*16K.
// 2 stages = 160KB smem -> 1 CTA/SM.
// ---------------------------------------------------------------------------
#define QSTG 81920u

__device__ __forceinline__ void qkv_stage_load(
    uint32_t sb, int stage, int tid, int m0,
    const __nv_bfloat16* __restrict__ B0h, const __nv_bfloat16* __restrict__ B0l,
    const __nv_bfloat16* __restrict__ B1h, const __nv_bfloat16* __restrict__ B1l,
    const __nv_bfloat16* __restrict__ B2h, const __nv_bfloat16* __restrict__ B2l,
    int c0)
{
    const uint32_t base = sb + (uint32_t)stage * QSTG;
#pragma unroll
    for (int it = 0; it < 4; it++) {                 // A: 1024 uint4 per buffer
        int idx = tid + it * 256;
        int m = idx >> 3, kv = idx & 7;
        uint32_t soff = (uint32_t)(m * 128 + ((kv ^ (m & 7)) << 4));
        size_t ga = (size_t)(m0 + m) * CC + c0 + kv * 8;
        CP_ASYNC16(base + soff,          g_xhi + ga);
        CP_ASYNC16(base + 16384 + soff,  g_xlo + ga);
    }
#pragma unroll
    for (int it = 0; it < 2; it++) {                 // B: 512 uint4 per buffer, x6
        int idx = tid + it * 256;
        int n = idx >> 3, kv = idx & 7;
        uint32_t soff = (uint32_t)(n * 128 + ((kv ^ (n & 7)) << 4));
        size_t gb = (size_t)n * CC + c0 + kv * 8;
        CP_ASYNC16(base + 32768 + soff,  B0h + gb);
        CP_ASYNC16(base + 40960 + soff,  B0l + gb);
        CP_ASYNC16(base + 49152 + soff,  B1h + gb);
        CP_ASYNC16(base + 57344 + soff,  B1l + gb);
        CP_ASYNC16(base + 65536 + soff,  B2h + gb);
        CP_ASYNC16(base + 73728 + soff,  B2l + gb);
    }
}

__global__ __launch_bounds__(256) void qkv_gemm()
{
    extern __shared__ unsigned char smem[];
    const uint32_t sb = smem_u32(smem);
    const int tid = threadIdx.x;
    const int wid = tid >> 5, lid = tid & 31;
    const int m0   = blockIdx.x * 128;
    const int head = blockIdx.y;
    const int warp_m = (wid & 3) * 32;
    const int warp_n = (wid >> 2) * 32;

    const size_t woff = (size_t)head * HS * CC;
    const __nv_bfloat16* B0h = g_wt_hi + woff;
    const __nv_bfloat16* B0l = g_wt_lo + woff;
    const __nv_bfloat16* B1h = g_wt_hi + (size_t)HH * HS * CC + woff;
    const __nv_bfloat16* B1l = g_wt_lo + (size_t)HH * HS * CC + woff;
    const __nv_bfloat16* B2h = g_wt_hi + (size_t)2 * HH * HS * CC + woff;
    const __nv_bfloat16* B2l = g_wt_lo + (size_t)2 * HH * HS * CC + woff;

    float acc[3][2][4][4];
#pragma unroll
    for (int z = 0; z < 3; z++)
#pragma unroll
        for (int i = 0; i < 2; i++)
#pragma unroll
            for (int j = 0; j < 4; j++)
#pragma unroll
                for (int r = 0; r < 4; r++) acc[z][i][j][r] = 0.f;

    qkv_stage_load(sb, 0, tid, m0, B0h, B0l, B1h, B1l, B2h, B2l, 0);
    CP_COMMIT();

    for (int it = 0; it < 16; it++) {
        const int cur = it & 1;
        CP_WAIT0();
        __syncthreads();
        if (it + 1 < 16) {
            qkv_stage_load(sb, cur ^ 1, tid, m0, B0h, B0l, B1h, B1l, B2h, B2l,
                           (it + 1) * 64);
            CP_COMMIT();
        }

        const uint32_t stb = sb + (uint32_t)cur * QSTG;
#pragma unroll
        for (int ks = 0; ks < 4; ks++) {
            const int kb = ks * 2 + (lid >> 4);
            uint32_t aHi[2][4], aLo[2][4];
#pragma unroll
            for (int i = 0; i < 2; i++) {
                int row = warp_m + i * 16 + (lid & 15);
                uint32_t ad = stb + (uint32_t)(row * 128 + ((kb ^ (row & 7)) << 4));
                LDSM4(aHi[i], ad);
                LDSM4(aLo[i], ad + 16384);
            }
#pragma unroll
            for (int z = 0; z < 3; z++) {
                uint32_t bHi[4][2], bLo[4][2];
                const uint32_t bbase = stb + 32768u + (uint32_t)z * 16384u;
#pragma unroll
                for (int nb = 0; nb < 2; nb++) {
                    int row = warp_n + nb * 16 + (lid & 15);
                    uint32_t ad = bbase + (uint32_t)(row * 128 + ((kb ^ (row & 7)) << 4));
                    uint32_t q[4];
                    LDSM4(q, ad);
                    bHi[nb*2][0] = q[0]; bHi[nb*2][1] = q[2];
                    bHi[nb*2+1][0] = q[1]; bHi[nb*2+1][1] = q[3];
                    LDSM4(q, ad + 8192);
                    bLo[nb*2][0] = q[0]; bLo[nb*2][1] = q[2];
                    bLo[nb*2+1][0] = q[1]; bLo[nb*2+1][1] = q[3];
                }
#pragma unroll
                for (int i = 0; i < 2; i++)
#pragma unroll
                    for (int j = 0; j < 4; j++) {
                        MMA_BF16(acc[z][i][j], aHi[i], bHi[j]);
                        MMA_BF16(acc[z][i][j], aLo[i], bHi[j]);
                        MMA_BF16(acc[z][i][j], aHi[i], bLo[j]);
                    }
            }
        }
    }

    const int g = lid >> 2, t4 = lid & 3;

    // ---- q / k epilogues: split to bf16 hi/lo, store [B,H,T,HS]
#pragma unroll
    for (int z = 0; z < 2; z++) {
        uint32_t* ohi = reinterpret_cast<uint32_t*>(z == 0 ? g_qhi : g_khi);
        uint32_t* olo = reinterpret_cast<uint32_t*>(z == 0 ? g_qlo : g_klo);
#pragma unroll
        for (int i = 0; i < 2; i++)
#pragma unroll
            for (int j = 0; j < 4; j++) {
                const int d = warp_n + j * 8 + t4 * 2;
                const int r0 = m0 + warp_m + i * 16 + g;
                uint32_t hi, lo;
                {
                    int b = r0 >> 11, tt = r0 & (TT - 1);
                    size_t o = ((((size_t)b * HH + head) * TT + tt) * HS + d) >> 1;
                    split2(acc[z][i][j][0], acc[z][i][j][1], hi, lo);
                    ohi[o] = hi; olo[o] = lo;
                }
                {
                    int r1 = r0 + 8;
                    int b = r1 >> 11, tt = r1 & (TT - 1);
                    size_t o = ((((size_t)b * HH + head) * TT + tt) * HS + d) >> 1;
                    split2(acc[z][i][j][2], acc[z][i][j][3], hi, lo);
                    ohi[o] = hi; olo[o] = lo;
                }
            }
    }

    // ---- v epilogue: stage fp32 tile (128x64) in smem, write transposed [B,H,HS,T]
    __syncthreads();
    float* ps = reinterpret_cast<float*>(smem);   // [128][64], col ^= (row&31); 32KB
#pragma unroll
    for (int i = 0; i < 2; i++)
#pragma unroll
        for (int j = 0; j < 4; j++) {
            int m = warp_m + i * 16 + g;
            int n = warp_n + j * 8 + t4 * 2;
            ps[m * 64 + (n ^ (m & 31))]            = acc[2][i][j][0];
            ps[m * 64 + ((n + 1) ^ (m & 31))]      = acc[2][i][j][1];
            int m8 = m + 8;
            ps[m8 * 64 + (n ^ (m8 & 31))]          = acc[2][i][j][2];
            ps[m8 * 64 + ((n + 1) ^ (m8 & 31))]    = acc[2][i][j][3];
        }
    __syncthreads();
    uint32_t* ohi = reinterpret_cast<uint32_t*>(g_vthi);
    uint32_t* olo = reinterpret_cast<uint32_t*>(g_vtlo);
#pragma unroll
    for (int it = 0; it < 16; it++) {             // 4096 (d, t-pair) pairs
        int u = tid + it * 256;
        int dl = u >> 6;                          // 0..63 (d)
        int tp = (u & 63) * 2;                    // local m (even)
        float v0 = ps[tp * 64 + (dl ^ (tp & 31))];
        float v1 = ps[(tp + 1) * 64 + (dl ^ ((tp + 1) & 31))];
        uint32_t hi, lo;
        split2(v0, v1, hi, lo);
        int tg = m0 + tp, b = tg >> 11, tt = tg & (TT - 1);
        size_t o = ((((size_t)b * HH + head) * HS + dl) * TT + tt) >> 1;
        ohi[o] = hi; olo[o] = lo;
    }
}

// ---------------------------------------------------------------------------
// Out-proj GEMM (R16 config, mode-1 path only): 2-stage cp.async, 2 CTAs/SM.
// Block 128x64x64; warps 4m x 2n (32x32).
// ---------------------------------------------------------------------------
#define GSTG 49152u

__device__ __forceinline__ void gemm_stage_load(
    uint32_t sb, int stage, int tid, int m0,
    const __nv_bfloat16* __restrict__ Ahi, const __nv_bfloat16* __restrict__ Alo,
    const __nv_bfloat16* __restrict__ Bhi, const __nv_bfloat16* __restrict__ Blo,
    int c0)
{
    const uint32_t base = sb + (uint32_t)stage * GSTG;
#pragma unroll
    for (int it = 0; it < 4; it++) {
        int idx = tid + it * 256;
        int m = idx >> 3, kv = idx & 7;
        uint32_t soff = (uint32_t)(m * 128 + ((kv ^ (m & 7)) << 4));
        size_t ga = (size_t)(m0 + m) * CC + c0 + kv * 8;
        CP_ASYNC16(base + soff,          Ahi + ga);
        CP_ASYNC16(base + 16384 + soff,  Alo + ga);
    }
#pragma unroll
    for (int it = 0; it < 2; it++) {
        int idx = tid + it * 256;
        int n = idx >> 3, kv = idx & 7;
        uint32_t soff = (uint32_t)(n * 128 + ((kv ^ (n & 7)) << 4));
        size_t gb = (size_t)n * CC + c0 + kv * 8;
        CP_ASYNC16(base + 32768 + soff,  Bhi + gb);
        CP_ASYNC16(base + 40960 + soff,  Blo + gb);
    }
}

__global__ __launch_bounds__(256, 2) void hmma_gemm(const float* __restrict__ bias,
                                                    float* __restrict__ out_direct)
{
    extern __shared__ unsigned char smem[];
    const uint32_t sb = smem_u32(smem);
    const int tid = threadIdx.x;
    const int wid = tid >> 5, lid = tid & 31;
    const int m0  = blockIdx.x * 128;
    const int warp_m = (wid & 3) * 32;
    const int warp_n = (wid >> 2) * 32;
    const int nbase  = blockIdx.y * 64;

    const __nv_bfloat16* Ahi = g_yhi;
    const __nv_bfloat16* Alo = g_ylo;
    const __nv_bfloat16* Bhi = g_wo_hi + (size_t)nbase * CC;
    const __nv_bfloat16* Blo = g_wo_lo + (size_t)nbase * CC;

    float acc[2][4][4];
#pragma unroll
    for (int i = 0; i < 2; i++)
#pragma unroll
        for (int j = 0; j < 4; j++)
#pragma unroll
            for (int r = 0; r < 4; r++) acc[i][j][r] = 0.f;

    gemm_stage_load(sb, 0, tid, m0, Ahi, Alo, Bhi, Blo, 0);
    CP_COMMIT();

    for (int it = 0; it < 16; it++) {
        const int cur = it & 1;
        CP_WAIT0();
        __syncthreads();
        if (it + 1 < 16) {
            gemm_stage_load(sb, cur ^ 1, tid, m0, Ahi, Alo, Bhi, Blo, (it + 1) * 64);
            CP_COMMIT();
        }

        const uint32_t stb = sb + (uint32_t)cur * GSTG;
#pragma unroll
        for (int ks = 0; ks < 4; ks++) {
            const int kb = ks * 2 + (lid >> 4);
            uint32_t aHi[2][4], aLo[2][4], bHi[4][2], bLo[4][2];
#pragma unroll
            for (int i = 0; i < 2; i++) {
                int row = warp_m + i * 16 + (lid & 15);
                uint32_t ad = stb + (uint32_t)(row * 128 + ((kb ^ (row & 7)) << 4));
                LDSM4(aHi[i], ad);
                LDSM4(aLo[i], ad + 16384);
            }
#pragma unroll
            for (int nb = 0; nb < 2; nb++) {
                int row = warp_n + nb * 16 + (lid & 15);
                uint32_t ad = stb + 32768 + (uint32_t)(row * 128 + ((kb ^ (row & 7)) << 4));
                uint32_t q[4];
                LDSM4(q, ad);
                bHi[nb*2][0] = q[0]; bHi[nb*2][1] = q[2];
                bHi[nb*2+1][0] = q[1]; bHi[nb*2+1][1] = q[3];
                LDSM4(q, ad + 8192);
                bLo[nb*2][0] = q[0]; bLo[nb*2][1] = q[2];
                bLo[nb*2+1][0] = q[1]; bLo[nb*2+1][1] = q[3];
            }
#pragma unroll
            for (int i = 0; i < 2; i++)
#pragma unroll
                for (int j = 0; j < 4; j++) {
                    MMA_BF16(acc[i][j], aHi[i], bHi[j]);
                    MMA_BF16(acc[i][j], aLo[i], bHi[j]);
                    MMA_BF16(acc[i][j], aHi[i], bLo[j]);
                }
        }
    }

    const int g = lid >> 2, t4 = lid & 3;
#pragma unroll
    for (int i = 0; i < 2; i++)
#pragma unroll
        for (int j = 0; j < 4; j++) {
            const int n = nbase + warp_n + j * 8 + t4 * 2;
            const int r0 = m0 + warp_m + i * 16 + g;
            const float b0 = bias[n], b1 = bias[n + 1];
            *reinterpret_cast<float2*>(out_direct + (size_t)r0 * CC + n) =
                make_float2(acc[i][j][0] + b0, acc[i][j][1] + b1);
            *reinterpret_cast<float2*>(out_direct + (size_t)(r0 + 8) * CC + n) =
                make_float2(acc[i][j][2] + b0, acc[i][j][3] + b1);
        }
}

// ---------------------------------------------------------------------------
// Flash attention (unchanged from R16): 4 warps x 32 q-rows, 2 CTAs/SM.
// ---------------------------------------------------------------------------
__device__ __forceinline__ void attn_stage_load(
    uint32_t sb, int stage, int tid,
    const __nv_bfloat16* __restrict__ Khi, const __nv_bfloat16* __restrict__ Klo,
    const __nv_bfloat16* __restrict__ Vhi, const __nv_bfloat16* __restrict__ Vlo,
    int k0)
{
    const uint32_t base = sb + 32768u + (uint32_t)stage * 32768u;
#pragma unroll
    for (int it = 0; it < 4; it++) {
        int idx = tid + it * 128;
        int m = idx >> 3, kv = idx & 7;
        uint32_t soff = (uint32_t)(m * 128 + ((kv ^ (m & 7)) << 4));
        size_t ga = (size_t)(k0 + m) * HS + kv * 8;
        size_t gv = (size_t)m * TT + k0 + kv * 8;
        CP_ASYNC16(base + soff,          Khi + ga);
        CP_ASYNC16(base + 8192  + soff,  Klo + ga);
        CP_ASYNC16(base + 16384 + soff,  Vhi + gv);
        CP_ASYNC16(base + 24576 + soff,  Vlo + gv);
    }
}

__global__ __launch_bounds__(128, 2) void attn_mma()
{
    extern __shared__ unsigned char smem[];
    const uint32_t sb = smem_u32(smem);
    const int tid = threadIdx.x, wid = tid >> 5, lid = tid & 31;
    const int gid = lid >> 2, t4 = lid & 3;
    const int qt = gridDim.x - 1 - blockIdx.x;    // long blocks first
    const int bh = blockIdx.y;
    const int q0 = qt * 128;
    const int wm = wid * 32;                      // warp's 32-row slice

    const __nv_bfloat16* Qhi = g_qhi + (size_t)bh * TT * HS;
    const __nv_bfloat16* Qlo = g_qlo + (size_t)bh * TT * HS;
    const __nv_bfloat16* Khi = g_khi + (size_t)bh * TT * HS;
    const __nv_bfloat16* Klo = g_klo + (size_t)bh * TT * HS;
    const __nv_bfloat16* Vhi = g_vthi + (size_t)bh * HS * TT;
    const __nv_bfloat16* Vlo = g_vtlo + (size_t)bh * HS * TT;

    // Prologue: Q tile + K/V stage 0 via cp.async (one group)
#pragma unroll
    for (int it = 0; it < 8; it++) {
        int idx = tid + it * 128;
        int m = idx >> 3, kv = idx & 7;
        uint32_t soff = (uint32_t)(m * 128 + ((kv ^ (m & 7)) << 4));
        size_t ga = (size_t)(q0 + m) * HS + kv * 8;
        CP_ASYNC16(sb + soff,          Qhi + ga);
        CP_ASYNC16(sb + 16384 + soff,  Qlo + ga);
    }
    attn_stage_load(sb, 0, tid, Khi, Klo, Vhi, Vlo, 0);
    CP_COMMIT();

    float O[2][8][4];
#pragma unroll
    for (int i = 0; i < 2; i++)
#pragma unroll
        for (int j = 0; j < 8; j++)
#pragma unroll
            for (int r = 0; r < 4; r++) O[i][j][r] = 0.f;
    float mr[2][2], lr[2][2];
#pragma unroll
    for (int i = 0; i < 2; i++) { mr[i][0] = mr[i][1] = -1e30f; lr[i][0] = lr[i][1] = 0.f; }

    const int jmax = 2 * qt + 1;

    for (int jt = 0; jt <= jmax; jt++) {
        const int k0 = jt * 64;
        CP_WAIT0();
        __syncthreads();
        if (jt < jmax) {
            attn_stage_load(sb, (jt + 1) & 1, tid, Khi, Klo, Vhi, Vlo, k0 + 64);
            CP_COMMIT();
        }

        const uint32_t kvb = sb + 32768u + (uint32_t)(jt & 1) * 32768u;

        // ---- S = Q * K^T (32 x 64 per warp)
        float sa[2][8][4];
#pragma unroll
        for (int i = 0; i < 2; i++)
#pragma unroll
            for (int j = 0; j < 8; j++)
#pragma unroll
                for (int r = 0; r < 4; r++) sa[i][j][r] = 0.f;

#pragma unroll
        for (int ks = 0; ks < 4; ks++) {
            const int kb = ks * 2 + (lid >> 4);
            uint32_t aH[2][4], aL[2][4];
#pragma unroll
            for (int i = 0; i < 2; i++) {
                int row = wm + i * 16 + (lid & 15);
                uint32_t ad = sb + (uint32_t)(row * 128 + ((kb ^ (row & 7)) << 4));
                LDSM4(aH[i], ad);
                LDSM4(aL[i], ad + 16384);
            }
#pragma unroll
            for (int nb = 0; nb < 4; nb++) {
                int row = nb * 16 + (lid & 15);
                uint32_t ad = kvb + (uint32_t)(row * 128 + ((kb ^ (row & 7)) << 4));
                uint32_t q[4], ql[4];
                LDSM4(q, ad);
                LDSM4(ql, ad + 8192);
                uint32_t bH0[2] = {q[0], q[2]},  bH1[2] = {q[1], q[3]};
                uint32_t bL0[2] = {ql[0], ql[2]}, bL1[2] = {ql[1], ql[3]};
#pragma unroll
                for (int i = 0; i < 2; i++) {
                    MMA_BF16(sa[i][nb*2],   aH[i], bH0);
                    MMA_BF16(sa[i][nb*2],   aL[i], bH0);
                    MMA_BF16(sa[i][nb*2],   aH[i], bL0);
                    MMA_BF16(sa[i][nb*2+1], aH[i], bH1);
                    MMA_BF16(sa[i][nb*2+1], aL[i], bH1);
                    MMA_BF16(sa[i][nb*2+1], aH[i], bL1);
                }
            }
        }

        // ---- scale + causal mask
#pragma unroll
        for (int i = 0; i < 2; i++)
#pragma unroll
            for (int j = 0; j < 8; j++)
#pragma unroll
                for (int r = 0; r < 4; r++) sa[i][j][r] *= 0.125f;

#pragma unroll
        for (int i = 0; i < 2; i++) {
            const int rbase = q0 + wm + i * 16;
            if (k0 + 63 > rbase) {
                const int r0 = rbase + gid, r1 = r0 + 8;
#pragma unroll
                for (int j = 0; j < 8; j++) {
                    int c = k0 + j * 8 + t4 * 2;
                    if (c > r0)         sa[i][j][0] = -1e30f;
                    if (c + 1 > r0)     sa[i][j][1] = -1e30f;
                    if (c > r1)         sa[i][j][2] = -1e30f;
                    if (c + 1 > r1)     sa[i][j][3] = -1e30f;
                }
            }
        }

        // ---- online softmax
#pragma unroll
        for (int i = 0; i < 2; i++) {
            float mx0 = -1e30f, mx1 = -1e30f;
#pragma unroll
            for (int j = 0; j < 8; j++) {
                mx0 = fmaxf(mx0, fmaxf(sa[i][j][0], sa[i][j][1]));
                mx1 = fmaxf(mx1, fmaxf(sa[i][j][2], sa[i][j][3]));
            }
            mx0 = fmaxf(mx0, __shfl_xor_sync(0xffffffffu, mx0, 1));
            mx0 = fmaxf(mx0, __shfl_xor_sync(0xffffffffu, mx0, 2));
            mx1 = fmaxf(mx1, __shfl_xor_sync(0xffffffffu, mx1, 1));
            mx1 = fmaxf(mx1, __shfl_xor_sync(0xffffffffu, mx1, 2));

            float mn0 = fmaxf(mr[i][0], mx0), mn1 = fmaxf(mr[i][1], mx1);
            float al0 = __expf(mr[i][0] - mn0), al1 = __expf(mr[i][1] - mn1);
            mr[i][0] = mn0; mr[i][1] = mn1;

            float ls0 = 0.f, ls1 = 0.f;
#pragma unroll
            for (int j = 0; j < 8; j++) {
                sa[i][j][0] = __expf(sa[i][j][0] - mn0);
                sa[i][j][1] = __expf(sa[i][j][1] - mn0);
                sa[i][j][2] = __expf(sa[i][j][2] - mn1);
                sa[i][j][3] = __expf(sa[i][j][3] - mn1);
                ls0 += sa[i][j][0] + sa[i][j][1];
                ls1 += sa[i][j][2] + sa[i][j][3];
            }
            ls0 += __shfl_xor_sync(0xffffffffu, ls0, 1);
            ls0 += __shfl_xor_sync(0xffffffffu, ls0, 2);
            ls1 += __shfl_xor_sync(0xffffffffu, ls1, 1);
            ls1 += __shfl_xor_sync(0xffffffffu, ls1, 2);
            lr[i][0] = lr[i][0] * al0 + ls0;
            lr[i][1] = lr[i][1] * al1 + ls1;

#pragma unroll
            for (int j = 0; j < 8; j++) {
                O[i][j][0] *= al0; O[i][j][1] *= al0;
                O[i][j][2] *= al1; O[i][j][3] *= al1;
            }
        }

        // ---- O += P * V^T  (P repacked C-frag -> A-frag, hi/lo split)
#pragma unroll
        for (int kc = 0; kc < 4; kc++) {
            uint32_t pH[2][4], pL[2][4];
#pragma unroll
            for (int i = 0; i < 2; i++) {
                split2(sa[i][2*kc][0],   sa[i][2*kc][1],   pH[i][0], pL[i][0]);
                split2(sa[i][2*kc][2],   sa[i][2*kc][3],   pH[i][1], pL[i][1]);
                split2(sa[i][2*kc+1][0], sa[i][2*kc+1][1], pH[i][2], pL[i][2]);
                split2(sa[i][2*kc+1][2], sa[i][2*kc+1][3], pH[i][3], pL[i][3]);
            }

            const int kb = kc * 2 + (lid >> 4);
#pragma unroll
            for (int nb = 0; nb < 4; nb++) {
                int row = nb * 16 + (lid & 15);
                uint32_t ad = kvb + 16384 + (uint32_t)(row * 128 + ((kb ^ (row & 7)) << 4));
                uint32_t q[4], ql[4];
                LDSM4(q, ad);
                LDSM4(ql, ad + 8192);
                uint32_t vH0[2] = {q[0], q[2]},  vH1[2] = {q[1], q[3]};
                uint32_t vL0[2] = {ql[0], ql[2]}, vL1[2] = {ql[1], ql[3]};
#pragma unroll
                for (int i = 0; i < 2; i++) {
                    MMA_BF16(O[i][nb*2],   pH[i], vH0);
                    MMA_BF16(O[i][nb*2],   pL[i], vH0);
                    MMA_BF16(O[i][nb*2],   pH[i], vL0);
                    MMA_BF16(O[i][nb*2+1], pH[i], vH1);
                    MMA_BF16(O[i][nb*2+1], pL[i], vH1);
                    MMA_BF16(O[i][nb*2+1], pH[i], vL1);
                }
            }
        }
    }

    // ---- epilogue: y = O / l, bf16 hi/lo, layout [B,T,C]
    const int b = bh >> 4, h = bh & 15;
    uint32_t* yhi = reinterpret_cast<uint32_t*>(g_yhi);
    uint32_t* ylo = reinterpret_cast<uint32_t*>(g_ylo);
#pragma unroll
    for (int i = 0; i < 2; i++) {
        const float inv0 = 1.f / lr[i][0], inv1 = 1.f / lr[i][1];
        const int t0 = q0 + wm + i * 16 + gid, t1 = t0 + 8;
#pragma unroll
        for (int j = 0; j < 8; j++) {
            int d = h * 64 + j * 8 + t4 * 2;
            uint32_t hi, lo;
            split2(O[i][j][0] * inv0, O[i][j][1] * inv0, hi, lo);
            size_t o0 = (((size_t)b * TT + t0) * CC + d) >> 1;
            yhi[o0] = hi; ylo[o0] = lo;
            split2(O[i][j][2] * inv1, O[i][j][3] * inv1, hi, lo);
            size_t o1 = (((size_t)b * TT + t1) * CC + d) >> 1;
            yhi[o1] = hi; ylo[o1] = lo;
        }
    }
}

// ---------------------------------------------------------------------------
extern "C" void kernel_launch(void* const* d_in, const int* in_sizes, int n_in,
                              void* d_out, int out_size)
{
    const float* x  = (const float*)d_in[0];
    const float* Wq = (const float*)d_in[1];
    const float* Wk = (const float*)d_in[2];
    const float* Wv = (const float*)d_in[3];
    const float* Wo = (const float*)d_in[4];
    const float* bo = (const float*)d_in[5];
    float* out = (float*)d_out;

    __nv_bfloat16 *xhi, *xlo, *wohi, *wolo;
    cudaGetSymbolAddress((void**)&xhi,  g_xhi);
    cudaGetSymbolAddress((void**)&xlo,  g_xlo);
    cudaGetSymbolAddress((void**)&wohi, g_wo_hi);
    cudaGetSymbolAddress((void**)&wolo, g_wo_lo);

    // Prep: split x, W^T (q,k,v), Wo into hi/lo bf16
    cvt_split<<<(MM * CC) / (256 * 4), 256>>>(x, xhi, xlo);
    cvt_w_t<<<dim3(CC / 32, HS / 32, HH * 3), dim3(32, 8)>>>(Wq, Wk, Wv);
    cvt_split<<<(CC * CC) / (256 * 4), 256>>>(Wo, wohi, wolo);

    cudaFuncSetAttribute(qkv_gemm,
                         cudaFuncAttributeMaxDynamicSharedMemorySize, 163840);
    cudaFuncSetAttribute(hmma_gemm,
                         cudaFuncAttributeMaxDynamicSharedMemorySize, 98304);
    cudaFuncSetAttribute(attn_mma,
                         cudaFuncAttributeMaxDynamicSharedMemorySize, 98304);

    // Fused QKV projection: A-frags reused for q, k, v (1024 blocks)
    qkv_gemm<<<dim3(MM / 128, HH), 256, 163840>>>();

    // Flash attention on tensor cores (4 warps x 32 rows)
    attn_mma<<<dim3(TT / 128, BB * HH), 128, 98304>>>();

    // Output projection
    hmma_gemm<<<dim3(MM / 128, CC / 64), 256, 98304>>>(bo, out);
}